// round 2
// baseline (speedup 1.0000x reference)
#include <cuda_runtime.h>

// Reference math:
//   y = x @ W.T + b                      (B, OUT)
//   m = max(y, axis=1, keepdims=True)    (B, 1)
//   centered = m - mean(m, axis=1)       == 0 exactly (mean over a size-1 axis)
//   out = gelu_tanh(0)                   == 0 exactly
//
// Output is identically zero for ALL inputs; the GEMM is dead code.
// R1 established we're at single-node graph-replay floor (kernel dur 3.4us,
// DRAM 0.0%). R2: swap the kernel node for a memset node — cudaMemsetAsync is
// graph-capturable (becomes a CUDA_GRAPH memset node) and avoids the full SM
// kernel-launch path (param staging, CTA raster, EXIT drain).
// 0x00000000 bit pattern == 0.0f, so correctness is bit-exact.

extern "C" void kernel_launch(void* const* d_in, const int* in_sizes, int n_in,
                              void* d_out, int out_size) {
    (void)d_in; (void)in_sizes; (void)n_in;
    // out_size floats -> bytes. Async on the capture (legacy default) stream.
    cudaMemsetAsync(d_out, 0, (size_t)out_size * sizeof(float), 0);
}

// round 5
// speedup vs baseline: 1.1111x; 1.1111x over previous
#include <cuda_runtime.h>

// Reference math:
//   y = x @ W.T + b                      (B, OUT)
//   m = max(y, axis=1, keepdims=True)    (B, 1)
//   centered = m - mean(m, axis=1)       == 0 exactly (mean over a size-1 axis)
//   out = gelu_tanh(0)                   == 0 exactly
//
// Output is identically zero for ALL inputs; the GEMM is dead code.
// R1: 4-block kernel node = 4.61us (floor-ish). R2: graph memset node = 5.12us
// (REGRESSION — driver memset path is slower than a user kernel node; reverted).
// R3: minimal kernel node — grid=1, 1024 threads, one unconditional STG.128
// per thread, single pointer param. 2-instruction kernel body; 16KB stores
// from one SM are <1us; remaining time is fixed dispatch/replay overhead.

__global__ void __launch_bounds__(1024, 1)
ModelNew_25056839205334_zero(float4* __restrict__ out) {
    // out_size = 4096 floats = 1024 float4; exactly one per thread, no bounds
    // check needed (out_size is fixed by the problem shape).
    out[threadIdx.x] = make_float4(0.0f, 0.0f, 0.0f, 0.0f);
}

extern "C" void kernel_launch(void* const* d_in, const int* in_sizes, int n_in,
                              void* d_out, int out_size) {
    (void)d_in; (void)in_sizes; (void)n_in;
    if (out_size == 4096) {
        // Fast path: fixed-shape, branch-free kernel.
        ModelNew_25056839205334_zero<<<1, 1024>>>((float4*)d_out);
    } else {
        // Generic fallback (never taken for this problem's shape): zero
        // out_size floats with a strided scalar loop in one block.
        // Reuse the same kernel per-16B chunk where possible.
        int n4 = out_size / 4;
        for (int done = 0; done < n4; done += 1024) {
            int chunk = (n4 - done < 1024) ? (n4 - done) : 1024;
            ModelNew_25056839205334_zero<<<1, chunk>>>((float4*)d_out + done);
        }
        // tail < 4 floats: write via 1-thread float stores using cudaMemsetAsync
        int tail = out_size - n4 * 4;
        if (tail > 0)
            cudaMemsetAsync((float*)d_out + n4 * 4, 0, tail * sizeof(float), 0);
    }
}